// round 10
// baseline (speedup 1.0000x reference)
#include <cuda_runtime.h>
#include <cuda_bf16.h>
#include <cstdint>

// Problem constants (fixed by setup_inputs):
//   encoder_output: (B=32, L_ENC=512, E=256) float32
//   durations:      (B=32, L_ENC=512) int32, values in [0, 8)
//   output:         (B=32, L_DEC=2048, E=256) float32
//
// out[b, d, :] = enc[b, l, :] where cs[l-1] <= d < cs[l]; 0 for d >= cs[511].

#define B_SZ    32
#define L_ENC   512
#define L_DEC   2048
#define E_DIM   256
#define E_VEC   (E_DIM / 4)          // 64 float4 per row
#define ROW_BYTES (E_DIM * 4)        // 1024 bytes per row
#define ROWS_PER_CTA 32
#define SEG     (L_ENC / ROWS_PER_CTA)   // 16 scatter segments per batch

// Per-batch inclusive cumsum of durations.
__device__ int g_cs[B_SZ * L_ENC];

// ---------------------------------------------------------------------------
// Kernel A: per-batch inclusive scan of durations. One block per batch.
// ---------------------------------------------------------------------------
__global__ void lr_cumsum_kernel(const int* __restrict__ dur)
{
    __shared__ int warp_sums[16];
    const int b    = blockIdx.x;
    const int t    = threadIdx.x;
    const int wid  = t >> 5;
    const int lane = t & 31;

    int v = dur[b * L_ENC + t];

    #pragma unroll
    for (int off = 1; off < 32; off <<= 1) {
        int u = __shfl_up_sync(0xffffffffu, v, off);
        if (lane >= off) v += u;
    }
    if (lane == 31) warp_sums[wid] = v;
    __syncthreads();

    if (wid == 0 && lane < 16) {
        int ws = warp_sums[lane];
        #pragma unroll
        for (int off = 1; off < 16; off <<= 1) {
            int u = __shfl_up_sync(0x0000ffffu, ws, off);
            if (lane >= off) ws += u;
        }
        warp_sums[lane] = ws - warp_sums[lane];   // exclusive prefix of sums
    }
    __syncthreads();

    g_cs[b * L_ENC + t] = v + warp_sums[wid];
}

// ---------------------------------------------------------------------------
// smem <-> u32 helper for PTX shared-space addressing.
// ---------------------------------------------------------------------------
__device__ __forceinline__ uint32_t smem_u32(const void* p)
{
    uint32_t a;
    asm("{ .reg .u64 t; cvta.to.shared.u64 t, %1; cvt.u32.u64 %0, t; }"
        : "=r"(a) : "l"(p));
    return a;
}

// 1KB bulk store: smem row -> gmem row, async proxy (no LSU per-128b cost).
__device__ __forceinline__ void bulk_store_row(void* gdst, uint32_t ssrc)
{
    asm volatile(
        "cp.async.bulk.global.shared::cta.bulk_group [%0], [%1], %2;"
        :: "l"(gdst), "r"(ssrc), "n"(ROW_BYTES) : "memory");
}

// ---------------------------------------------------------------------------
// Kernel B: bulk-async scatter. Grid (SEG+1, B), 512 threads.
//
// x < SEG: segment of 32 encoder rows. Stage rows in smem (coalesced LDG),
// stage cumsum slice, fence to async proxy, then warp 0 lane l owns enc row
// l: for each decoder row d in [cs[l-1], cs[l]) it issues a 1KB bulk store
// from the staged smem row.
//
// x == SEG: padding. Zero smem row bulk-stored over [total, L_DEC).
// ---------------------------------------------------------------------------
__global__ void __launch_bounds__(512)
lr_scatter_kernel(const float4* __restrict__ enc, float4* __restrict__ out)
{
    __shared__ float4 s_rows[ROWS_PER_CTA + 1][E_VEC];   // +1 = zero row
    __shared__ int    s_cs[ROWS_PER_CTA + 1];

    const int b = blockIdx.y;
    const int x = blockIdx.x;
    const int t = threadIdx.x;

    float4* out_b = out + (long)b * L_DEC * E_VEC;
    const uint32_t s_base = smem_u32(&s_rows[0][0]);

    if (x < SEG) {
        const int l0 = x * ROWS_PER_CTA;

        // Stage 32 enc rows (2048 float4) coalesced: 4 per thread.
        const float4* enc_seg = enc + ((long)(b * L_ENC + l0)) * E_VEC;
        #pragma unroll
        for (int k = 0; k < 4; ++k) {
            const int idx = t + k * 512;              // 0..2047
            s_rows[idx >> 6][idx & 63] = enc_seg[idx];
        }
        // Zero row (row index 32).
        if (t < E_VEC)
            s_rows[ROWS_PER_CTA][t] = make_float4(0.f, 0.f, 0.f, 0.f);
        // Cumsum slice cs[l0-1 .. l0+31].
        if (t <= ROWS_PER_CTA) {
            const int idx = l0 - 1 + t;
            s_cs[t] = (idx >= 0) ? g_cs[b * L_ENC + idx] : 0;
        }
        __syncthreads();
        // Make generic-proxy smem writes visible to the async proxy.
        asm volatile("fence.proxy.async.shared::cta;" ::: "memory");

        if (t < ROWS_PER_CTA) {                       // warp 0 (+ lanes 0..31)
            int excl = s_cs[t];
            int incl = s_cs[t + 1];
            if (excl > L_DEC) excl = L_DEC;
            if (incl > L_DEC) incl = L_DEC;
            const uint32_t srow = s_base + (uint32_t)t * ROW_BYTES;
            for (int d = excl; d < incl; ++d)
                bulk_store_row(out_b + (long)d * E_VEC, srow);

            asm volatile("cp.async.bulk.commit_group;" ::: "memory");
            asm volatile("cp.async.bulk.wait_group.read 0;" ::: "memory");
        }
        __syncthreads();
    } else {
        // ---- padding path ----
        if (t < E_VEC)
            s_rows[0][t] = make_float4(0.f, 0.f, 0.f, 0.f);
        __syncthreads();
        asm volatile("fence.proxy.async.shared::cta;" ::: "memory");

        const int total = g_cs[b * L_ENC + (L_ENC - 1)];
        const int d0 = total < L_DEC ? total : L_DEC;

        bool issued = false;
        for (int d = d0 + t; d < L_DEC; d += 512) {
            bulk_store_row(out_b + (long)d * E_VEC, s_base);
            issued = true;
        }
        if (issued) {
            asm volatile("cp.async.bulk.commit_group;" ::: "memory");
            asm volatile("cp.async.bulk.wait_group.read 0;" ::: "memory");
        }
        __syncthreads();
    }
}

// ---------------------------------------------------------------------------
extern "C" void kernel_launch(void* const* d_in, const int* in_sizes, int n_in,
                              void* d_out, int out_size)
{
    const float* enc = (const float*)d_in[0];     // (B, L_ENC, E)
    const int*   dur = (const int*)d_in[1];       // (B, L_ENC) int32
    (void)in_sizes; (void)n_in; (void)out_size;

    lr_cumsum_kernel<<<B_SZ, L_ENC>>>(dur);

    dim3 grid(SEG + 1, B_SZ);
    lr_scatter_kernel<<<grid, 512>>>((const float4*)enc, (float4*)d_out);
}

// round 11
// speedup vs baseline: 1.1081x; 1.1081x over previous
#include <cuda_runtime.h>
#include <cuda_bf16.h>
#include <cstdint>

// Problem constants (fixed by setup_inputs):
//   encoder_output: (B=32, L_ENC=512, E=256) float32
//   durations:      (B=32, L_ENC=512) int32, values in [0, 8)
//   output:         (B=32, L_DEC=2048, E=256) float32
//
// out[b, d, :] = enc[b, l, :] where cs[l-1] <= d < cs[l]; 0 for d >= cs[511].

#define B_SZ    32
#define L_ENC   512
#define L_DEC   2048
#define E_DIM   256
#define E_VEC   (E_DIM / 4)          // 64 float4 per row
#define ROW_BYTES (E_DIM * 4)        // 1024 bytes per row
#define ROWS_PER_CTA 32
#define SEG     (L_ENC / ROWS_PER_CTA)   // 16 scatter segments per batch
#define MAX_SPAN 256                  // 32 rows x dur<8 => span <= 224

__device__ __forceinline__ uint32_t smem_u32(const void* p)
{
    uint32_t a;
    asm("{ .reg .u64 t; cvta.to.shared.u64 t, %1; cvt.u32.u64 %0, t; }"
        : "=r"(a) : "l"(p));
    return a;
}

__device__ __forceinline__ void bulk_store_row(void* gdst, uint32_t ssrc)
{
    asm volatile(
        "cp.async.bulk.global.shared::cta.bulk_group [%0], [%1], %2;"
        :: "l"(gdst), "r"(ssrc), "n"(ROW_BYTES) : "memory");
}

// ---------------------------------------------------------------------------
// Single fused kernel. Grid (SEG+1, B), 512 threads.
// Every block: load batch durations (2KB), block-wide scan -> s_cs[512].
// x < SEG : stage 32 enc rows in smem, build span map, 256 threads each
//           issue ONE 1KB bulk store (balanced, parallel TMA feed).
// x == SEG: zero-fill rows [total, L_DEC) with bulk stores of a zero row.
// ---------------------------------------------------------------------------
__global__ void __launch_bounds__(512)
lr_fused_kernel(const float4* __restrict__ enc,
                const int*    __restrict__ dur,
                float4* __restrict__ out)
{
    __shared__ float4 s_rows[ROWS_PER_CTA][E_VEC];   // 32 KB staged enc rows
    __shared__ int    s_cs[L_ENC];                   // full batch cumsum
    __shared__ int    s_map[MAX_SPAN];               // span row -> local enc row
    __shared__ int    s_wsum[16];

    const int b    = blockIdx.y;
    const int x    = blockIdx.x;
    const int t    = threadIdx.x;
    const int wid  = t >> 5;
    const int lane = t & 31;

    float4* out_b = out + (long)b * L_DEC * E_VEC;

    // ---- 1. block-wide inclusive scan of this batch's durations ----
    int v = dur[b * L_ENC + t];
    #pragma unroll
    for (int off = 1; off < 32; off <<= 1) {
        int u = __shfl_up_sync(0xffffffffu, v, off);
        if (lane >= off) v += u;
    }
    if (lane == 31) s_wsum[wid] = v;
    __syncthreads();
    if (wid == 0 && lane < 16) {
        int ws = s_wsum[lane];
        #pragma unroll
        for (int off = 1; off < 16; off <<= 1) {
            int u = __shfl_up_sync(0x0000ffffu, ws, off);
            if (lane >= off) ws += u;
        }
        s_wsum[lane] = ws - s_wsum[lane];            // exclusive prefix
    }
    __syncthreads();
    s_cs[t] = v + s_wsum[wid];

    if (x < SEG) {
        // ---- 2. stage 32 enc rows (2048 float4, coalesced, 4/thread) ----
        const int l0 = x * ROWS_PER_CTA;
        const float4* enc_seg = enc + ((long)(b * L_ENC + l0)) * E_VEC;
        #pragma unroll
        for (int k = 0; k < 4; ++k) {
            const int idx = t + k * 512;             // 0..2047
            s_rows[idx >> 6][idx & 63] = enc_seg[idx];
        }
        __syncthreads();                             // s_cs + s_rows ready

        // ---- 3. build span map: local decoder row -> local enc row ----
        const int span_start = (l0 == 0) ? 0 : s_cs[l0 - 1];
        int span_end = s_cs[l0 + ROWS_PER_CTA - 1];
        if (span_end > L_DEC) span_end = L_DEC;

        if (t < ROWS_PER_CTA) {
            const int l  = l0 + t;
            int lo = (l == 0) ? 0 : s_cs[l - 1];
            int hi = s_cs[l];
            if (hi > L_DEC) hi = L_DEC;
            for (int d = lo; d < hi; ++d)
                s_map[d - span_start] = t;
        }
        __syncthreads();
        asm volatile("fence.proxy.async.shared::cta;" ::: "memory");

        // ---- 4. one bulk store per thread (t < span length) ----
        const uint32_t s_base = smem_u32(&s_rows[0][0]);
        const int d = span_start + t;
        if (t < MAX_SPAN && d < span_end) {
            const uint32_t srow = s_base + (uint32_t)s_map[t] * ROW_BYTES;
            bulk_store_row(out_b + (long)d * E_VEC, srow);
            asm volatile("cp.async.bulk.commit_group;" ::: "memory");
            asm volatile("cp.async.bulk.wait_group.read 0;" ::: "memory");
        }
        __syncthreads();                             // smem stays live
    } else {
        // ---- padding path: zero rows [total, L_DEC) ----
        if (t < E_VEC)
            s_rows[0][t] = make_float4(0.f, 0.f, 0.f, 0.f);
        __syncthreads();
        asm volatile("fence.proxy.async.shared::cta;" ::: "memory");

        int total = s_cs[L_ENC - 1];
        if (total > L_DEC) total = L_DEC;

        const uint32_t s_base = smem_u32(&s_rows[0][0]);
        bool issued = false;
        for (int d = total + t; d < L_DEC; d += 512) {
            bulk_store_row(out_b + (long)d * E_VEC, s_base);
            issued = true;
        }
        if (issued) {
            asm volatile("cp.async.bulk.commit_group;" ::: "memory");
            asm volatile("cp.async.bulk.wait_group.read 0;" ::: "memory");
        }
        __syncthreads();
    }
}

// ---------------------------------------------------------------------------
extern "C" void kernel_launch(void* const* d_in, const int* in_sizes, int n_in,
                              void* d_out, int out_size)
{
    const float* enc = (const float*)d_in[0];     // (B, L_ENC, E)
    const int*   dur = (const int*)d_in[1];       // (B, L_ENC) int32
    (void)in_sizes; (void)n_in; (void)out_size;

    dim3 grid(SEG + 1, B_SZ);
    lr_fused_kernel<<<grid, 512>>>((const float4*)enc, dur, (float4*)d_out);
}

// round 12
// speedup vs baseline: 1.4138x; 1.2759x over previous
#include <cuda_runtime.h>
#include <cuda_bf16.h>

// Problem constants (fixed by setup_inputs):
//   encoder_output: (B=32, L_ENC=512, E=256) float32
//   durations:      (B=32, L_ENC=512) int32, values in [0, 8)
//   output:         (B=32, L_DEC=2048, E=256) float32
//
// out[b, d, :] = enc[b, l, :] where cs[l-1] <= d < cs[l]; 0 for d >= cs[511].

#define B_SZ    32
#define L_ENC   512
#define L_DEC   2048
#define E_DIM   256
#define E_VEC   (E_DIM / 4)            // 64 float4 per row
#define ROWS_PER_BLOCK 64              // decoder rows per block
#define BLOCKS_PER_BATCH (L_DEC / ROWS_PER_BLOCK)   // 32
#define ROWS_PER_GROUP 8               // 8 groups x 8 rows = 64

// ---------------------------------------------------------------------------
// Single fused kernel. Grid = B * 32 blocks, 512 threads.
// Per block:
//  1. load batch durations (2KB, L2-hot) + block-wide inclusive scan
//  2. scatter s_map[64]: decoder row (within block range) -> enc row, -1 pad
//  3. gather: 8 groups of 64 lanes copy 8 consecutive 1KB rows each
// ---------------------------------------------------------------------------
__global__ void __launch_bounds__(512)
lr_fused_kernel(const float4* __restrict__ enc,
                const int*    __restrict__ dur,
                float4* __restrict__ out)
{
    __shared__ int s_wsum[16];
    __shared__ int s_map[ROWS_PER_BLOCK];

    const int bid  = blockIdx.x;
    const int b    = bid >> 5;               // batch (32 blocks per batch)
    const int blk  = bid & 31;               // block within batch
    const int base = blk * ROWS_PER_BLOCK;   // decoder row base (0..1984)
    const int t    = threadIdx.x;
    const int wid  = t >> 5;
    const int lane = t & 31;

    // ---- 1. block-wide inclusive scan of this batch's 512 durations ----
    const int my_dur = dur[b * L_ENC + t];
    int v = my_dur;
    #pragma unroll
    for (int off = 1; off < 32; off <<= 1) {
        int u = __shfl_up_sync(0xffffffffu, v, off);
        if (lane >= off) v += u;
    }
    if (lane == 31) s_wsum[wid] = v;

    // init s_map while waiting (before barrier is fine: distinct smem)
    if (t < ROWS_PER_BLOCK) s_map[t] = -1;
    __syncthreads();

    if (wid == 0 && lane < 16) {
        int ws = s_wsum[lane];
        #pragma unroll
        for (int off = 1; off < 16; off <<= 1) {
            int u = __shfl_up_sync(0x0000ffffu, ws, off);
            if (lane >= off) ws += u;
        }
        s_wsum[lane] = ws - s_wsum[lane];    // exclusive prefix of warp sums
    }
    __syncthreads();

    const int incl = v + s_wsum[wid];        // inclusive cumsum at enc row t
    const int excl = incl - my_dur;

    // ---- 2. scatter: enc row t covers decoder rows [excl, incl) ----
    {
        int lo = excl > base ? excl : base;
        int hi = incl < base + ROWS_PER_BLOCK ? incl : base + ROWS_PER_BLOCK;
        for (int d = lo; d < hi; ++d)
            s_map[d - base] = t;             // each map slot written once
    }
    __syncthreads();

    // ---- 3. gather: group g copies rows base + g*8 .. +7 ----
    const int group = t >> 6;                // 0..7
    const int glane = t & 63;                // 0..63
    const int r0    = group * ROWS_PER_GROUP;

    int src[ROWS_PER_GROUP];
    #pragma unroll
    for (int j = 0; j < ROWS_PER_GROUP; ++j)
        src[j] = s_map[r0 + j];              // broadcast LDS

    float4 vv[ROWS_PER_GROUP];
    #pragma unroll
    for (int j = 0; j < ROWS_PER_GROUP; ++j) {
        const int safe = src[j] >= 0 ? src[j] : 0;
        vv[j] = __ldg(enc + ((long)(b * L_ENC + safe)) * E_VEC + glane);
    }

    float4* out_rows = out + ((long)(b * L_DEC + base + r0)) * E_VEC;
    #pragma unroll
    for (int j = 0; j < ROWS_PER_GROUP; ++j) {
        if (src[j] < 0) vv[j] = make_float4(0.f, 0.f, 0.f, 0.f);
        out_rows[(long)j * E_VEC + glane] = vv[j];
    }
}

// ---------------------------------------------------------------------------
extern "C" void kernel_launch(void* const* d_in, const int* in_sizes, int n_in,
                              void* d_out, int out_size)
{
    const float* enc = (const float*)d_in[0];     // (B, L_ENC, E)
    const int*   dur = (const int*)d_in[1];       // (B, L_ENC) int32
    (void)in_sizes; (void)n_in; (void)out_size;

    lr_fused_kernel<<<B_SZ * BLOCKS_PER_BATCH, 512>>>((const float4*)enc,
                                                      dur, (float4*)d_out);
}